// round 6
// baseline (speedup 1.0000x reference)
#include <cuda_runtime.h>
#include <cuda_fp16.h>
#include <cstdint>

#define BB 4
#define CC 256
#define OO 256
#define HH 192
#define WW 192
#define HWP (HH*WW)          // 36864
#define KK 2304              // 9 taps * 256 ch
#define MT 128               // pixels per CTA tile
#define NCHUNK 36
#define SA 72                // A padded row stride (fp16 elems), 144B

// ---- scratch (__device__ globals: allocation-free) ----
__device__ float g_xn[(size_t)BB*HWP*CC];     // NHWC x
__device__ float g_sx[BB*HWP];
__device__ float g_sy[BB*HWP];
__device__ __half g_wh[OO*KK];                // weight hi fp16, [o][t*256+c]
__device__ __half g_wl[OO*KK];                // weight lo fp16
__device__ float g_spwt[2*9*256];             // sp weights [ch][tap][c]

// ================= helpers (plain sm_80+ PTX only) =================
__device__ __forceinline__ uint32_t s2u(const void* p) {
    uint32_t a;
    asm("{ .reg .u64 t; cvta.to.shared.u64 t, %1; cvt.u32.u64 %0, t; }" : "=r"(a) : "l"(p));
    return a;
}
__device__ __forceinline__ uint32_t hpack(float lo, float hi) {
    uint32_t r;
    asm("cvt.rn.f16x2.f32 %0, %1, %2;" : "=r"(r) : "f"(hi), "f"(lo));
    return r;
}
__device__ __forceinline__ void sts64(uint32_t a, uint32_t x, uint32_t y) {
    asm volatile("st.shared.v2.b32 [%0], {%1, %2};" :: "r"(a), "r"(x), "r"(y) : "memory");
}
__device__ __forceinline__ void ldm4(uint32_t* r, uint32_t a) {
    asm volatile("ldmatrix.sync.aligned.m8n8.x4.shared.b16 {%0,%1,%2,%3}, [%4];"
                 : "=r"(r[0]), "=r"(r[1]), "=r"(r[2]), "=r"(r[3]) : "r"(a));
}
__device__ __forceinline__ void mma16816(float* d, const uint32_t* a, uint32_t b0, uint32_t b1) {
    asm volatile("mma.sync.aligned.m16n8k16.row.col.f32.f16.f16.f32 "
                 "{%0,%1,%2,%3}, {%4,%5,%6,%7}, {%8,%9}, {%0,%1,%2,%3};"
                 : "+f"(d[0]), "+f"(d[1]), "+f"(d[2]), "+f"(d[3])
                 : "r"(a[0]), "r"(a[1]), "r"(a[2]), "r"(a[3]), "r"(b0), "r"(b1));
}
__device__ __forceinline__ void cpasync16(uint32_t dst, const void* src) {
    asm volatile("cp.async.cg.shared.global [%0], [%1], 16;"
                 :: "r"(dst), "l"(__cvta_generic_to_global(src)) : "memory");
}
#define BARSYNC(id) asm volatile("bar.sync %0, 640;"   :: "r"(id) : "memory")
#define BARARR(id)  asm volatile("bar.arrive %0, 640;" :: "r"(id) : "memory")

// k_main smem layout (bytes): A stages 2x18432, then B stages 2x(32K hi + 32K lo)
#define OFF_A(s)   ((s)*18432)
#define OFF_BHI(s) (36864 + (s)*65536)
#define OFF_BLO(s) (36864 + (s)*65536 + 32768)
#define SMEM_DYN 167936

// ============ K1: NCHW -> NHWC transpose ============
__global__ void k_transpose(const float* __restrict__ x) {
    __shared__ float tile[32][33];
    int hw0 = blockIdx.x * 32, c0 = blockIdx.y * 32, b = blockIdx.z;
    int tx = threadIdx.x, ty = threadIdx.y;
#pragma unroll
    for (int i = 0; i < 4; ++i)
        tile[ty + i*8][tx] = x[(b*CC + c0 + ty + i*8)*HWP + hw0 + tx];
    __syncthreads();
#pragma unroll
    for (int i = 0; i < 4; ++i)
        g_xn[((size_t)b*HWP + hw0 + ty + i*8)*CC + c0 + tx] = tile[tx][ty + i*8];
}

// ============ K2: weight split to fp16 hi/lo, [o][t*256+c] ============
__global__ void k_wsplit(const float* __restrict__ w) {
    int idx = blockIdx.x*256 + threadIdx.x;
    int o = idx / KK, k = idx - o*KK;
    int t = k >> 8, c = k & 255;
    float v = w[(o*CC + c)*9 + t];
    __half h = __float2half_rn(v);
    g_wh[idx] = h;
    g_wl[idx] = __float2half_rn(v - __half2float(h));
}

// ============ K2b: sp weight transpose [ch][tap][c] ============
__global__ void k_spwt(const float* __restrict__ spw) {
    int i = blockIdx.x*256 + threadIdx.x;
    if (i >= 2*9*256) return;
    int ch = i / 2304, rem = i - ch*2304;
    int t = rem >> 8, c = rem & 255;
    g_spwt[i] = spw[(ch*CC + c)*9 + t];
}

// ============ K3: scale-predictor conv, tiled in smem ============
// block = 256 thr = 16x16 pixel tile; halo 18x18; 8-ch chunks, padded stride 12.
__global__ __launch_bounds__(256)
void k_spconv(const float* __restrict__ spb) {
    __shared__ float ws[2*9*256];       // 18 KB
    __shared__ float xs[324*12];        // 15.2 KB, row stride 12 floats
    int tid = threadIdx.x;
    for (int i = tid; i < 2*9*256; i += 256) ws[i] = g_spwt[i];

    int bx = blockIdx.x % (WW/16), rem = blockIdx.x / (WW/16);
    int by = rem % (HH/16), b = rem / (HH/16);
    int x0 = bx*16, y0 = by*16;
    int tx = tid & 15, ty = tid >> 4;

    float a0 = 0.f, a1 = 0.f;
    for (int cc = 0; cc < 32; ++cc) {
        __syncthreads();
        // load halo tile chunk: 324 px x 8 ch (2 float4 each)
        for (int tau = tid; tau < 648; tau += 256) {
            int pix = tau >> 1, half = tau & 1;
            int gy = y0 + pix/18 - 1, gx = x0 + (pix - (pix/18)*18) - 1;
            float4 v = make_float4(0.f, 0.f, 0.f, 0.f);
            if (gy >= 0 && gy < HH && gx >= 0 && gx < WW)
                v = *(const float4*)(g_xn + ((size_t)b*HWP + gy*WW + gx)*CC + cc*8 + half*4);
            *(float4*)(xs + pix*12 + half*4) = v;
        }
        __syncthreads();
#pragma unroll
        for (int t = 0; t < 9; ++t) {
            int pix = (ty + t/3)*18 + tx + t%3;
            float4 xv0 = *(const float4*)(xs + pix*12);
            float4 xv1 = *(const float4*)(xs + pix*12 + 4);
            const float* w0 = ws + t*256 + cc*8;
            const float* w1 = ws + 2304 + t*256 + cc*8;
            float4 wa0 = *(const float4*)w0, wa1 = *(const float4*)(w0+4);
            float4 wb0 = *(const float4*)w1, wb1 = *(const float4*)(w1+4);
            a0 += xv0.x*wa0.x + xv0.y*wa0.y + xv0.z*wa0.z + xv0.w*wa0.w
                + xv1.x*wa1.x + xv1.y*wa1.y + xv1.z*wa1.z + xv1.w*wa1.w;
            a1 += xv0.x*wb0.x + xv0.y*wb0.y + xv0.z*wb0.z + xv0.w*wb0.w
                + xv1.x*wb1.x + xv1.y*wb1.y + xv1.z*wb1.z + xv1.w*wb1.w;
        }
    }
    int p = (b*HH + y0+ty)*WW + x0+tx;
    g_sx[p] = expf(fminf(fmaxf(a0 + spb[0], -2.f), 2.f));
    g_sy[p] = expf(fminf(fmaxf(a1 + spb[1], -2.f), 2.f));
}

// ============ K4: warp-specialized gather + fp16 2-term HMMA ============
// 640 thr: warps 0-15 consumers (4M x 4N), warps 16-19 producers (128 thr).
// Double-buffered A (gather) and B (cp.async). Named barriers FULL/EMPTY.
__global__ void __launch_bounds__(640, 1)
k_main(const float* __restrict__ bias, float* __restrict__ out) {
    extern __shared__ char sm[];
    const uint32_t SMB = s2u(sm);

    const int tid  = threadIdx.x;
    const int wid  = tid >> 5, lane = tid & 31;
    const int m0 = blockIdx.x * MT;
    const int b  = m0 / HWP;
    const int pb = b * HWP;
    const int p0 = m0 - pb;

    if (wid >= 16) {
        // ================= PRODUCER (128 threads) =================
        const int ptid = tid - 512;
        const int p = m0 + ptid;
        const int r = p - pb;
        const int y = r / WW, xx = r - y*WW;
        const float sxv = g_sx[p], syv = g_sy[p];
        int o00 = 0, o01 = 0, o10 = 0, o11 = 0;
        float w00 = 0.f, w01 = 0.f, w10 = 0.f, w11 = 0.f;

        for (int ic = 0; ic < NCHUNK; ++ic) {
            const int s = ic & 1;
            if ((ic & 3) == 0) {
                int t = ic >> 2;
                float cx = (float)(t % 3 - 1), cy = (float)(t / 3 - 1);
                float gx = fminf(fmaxf((float)xx + cx*sxv, 0.f), (float)(WW-1));
                float gy = fminf(fmaxf((float)y  + cy*syv, 0.f), (float)(HH-1));
                float x0f = floorf(gx), y0f = floorf(gy);
                float wx = gx - x0f, wy = gy - y0f;
                int ix0 = (int)x0f, iy0 = (int)y0f;
                int ix1 = min(ix0+1, WW-1), iy1 = min(iy0+1, HH-1);
                int r0 = pb + iy0*WW, r1 = pb + iy1*WW;
                o00 = (r0 + ix0) * CC;  o01 = (r0 + ix1) * CC;
                o10 = (r1 + ix0) * CC;  o11 = (r1 + ix1) * CC;
                w00 = (1.f-wx)*(1.f-wy); w01 = wx*(1.f-wy);
                w10 = (1.f-wx)*wy;       w11 = wx*wy;
            }
            if (ic >= 2) BARSYNC(3 + s);          // wait buffer s consumed

            // B tiles via cp.async (hi+lo, 256 rows x 128B, XOR swizzle)
            const uint32_t BH = SMB + OFF_BHI(s), BL = SMB + OFF_BLO(s);
#pragma unroll
            for (int it = 0; it < 32; ++it) {
                int tau = ptid + it*128;
                int tl = tau >> 11;
                int rr = (tau >> 3) & 255;
                int u  = tau & 7;
                const __half* src = (tl ? g_wl : g_wh) + (size_t)rr*KK + ic*64 + u*8;
                uint32_t off = (uint32_t)(rr*128 + u*16);
                cpasync16((tl ? BL : BH) + (off ^ ((off >> 3) & 0x70u)), src);
            }
            asm volatile("cp.async.commit_group;" ::: "memory");

            // A gather: this thread's pixel, 64 channels
            const int cbase = (ic & 3) * 64;
            const uint32_t arow = SMB + OFF_A(s) + (uint32_t)ptid * (SA*2);
#pragma unroll 4
            for (int j = 0; j < 16; ++j) {
                int cb = cbase + j*4;
                const float4 v00 = *(const float4*)(g_xn + (size_t)o00 + cb);
                const float4 v01 = *(const float4*)(g_xn + (size_t)o01 + cb);
                const float4 v10 = *(const float4*)(g_xn + (size_t)o10 + cb);
                const float4 v11 = *(const float4*)(g_xn + (size_t)o11 + cb);
                float f0 = w00*v00.x + w01*v01.x + w10*v10.x + w11*v11.x;
                float f1 = w00*v00.y + w01*v01.y + w10*v10.y + w11*v11.y;
                float f2 = w00*v00.z + w01*v01.z + w10*v10.z + w11*v11.z;
                float f3 = w00*v00.w + w01*v01.w + w10*v10.w + w11*v11.w;
                sts64(arow + j*8, hpack(f0, f1), hpack(f2, f3));
            }
            asm volatile("cp.async.wait_group 0;" ::: "memory");
            BARARR(1 + s);                        // buffer s full
        }
        // fall through to epilogue barriers
        __syncthreads();
        __syncthreads();
    } else {
        // ================= CONSUMER (512 threads, 16 warps) =================
        const int wm = wid & 3;            // 32-row group
        const int wn = wid >> 2;           // 64-col group
        const int lrow = lane & 7;
        const int a_row16 = lrow + ((lane >> 3) & 1) * 8;
        const int a_k8    = (lane >> 4) * 8;
        const uint32_t aoff0 = (uint32_t)((wm*32 + a_row16) * SA + a_k8) * 2;
        const uint32_t aoff1 = aoff0 + 16*SA*2;
        const int b_n   = (lane >> 4) * 8 + lrow;
        const int brow  = wn*64 + b_n;
        const uint32_t bbase = (uint32_t)brow * 128u;
        const uint32_t bxor  = ((uint32_t)brow & 7u) << 4;
        const uint32_t bkk   = ((lane >> 3) & 1) * 16;

        float acc[2][8][4];
#pragma unroll
        for (int i = 0; i < 2; ++i)
#pragma unroll
            for (int j = 0; j < 8; ++j)
#pragma unroll
                for (int q = 0; q < 4; ++q) acc[i][j][q] = 0.f;

        for (int ic = 0; ic < NCHUNK; ++ic) {
            const int s = ic & 1;
            BARSYNC(1 + s);                       // wait buffer s full
            const uint32_t AT = SMB + OFF_A(s);
            const uint32_t BH = SMB + OFF_BHI(s), BL = SMB + OFF_BLO(s);
#pragma unroll
            for (int ks = 0; ks < 4; ++ks) {
                uint32_t a0[4], a1[4];
                ldm4(a0, AT + aoff0 + ks*32);
                ldm4(a1, AT + aoff1 + ks*32);
                uint32_t koff = ((uint32_t)(ks*32) + bkk) ^ bxor;
#pragma unroll
                for (int nt = 0; nt < 4; ++nt) {
                    uint32_t bh[4], bl[4];
                    ldm4(bh, BH + bbase + nt*2048 + koff);
                    ldm4(bl, BL + bbase + nt*2048 + koff);
                    int n0 = nt*2;
                    mma16816(acc[0][n0],   a0, bh[0], bh[1]);
                    mma16816(acc[0][n0+1], a0, bh[2], bh[3]);
                    mma16816(acc[1][n0],   a1, bh[0], bh[1]);
                    mma16816(acc[1][n0+1], a1, bh[2], bh[3]);
                    mma16816(acc[0][n0],   a0, bl[0], bl[1]);
                    mma16816(acc[0][n0+1], a0, bl[2], bl[3]);
                    mma16816(acc[1][n0],   a1, bl[0], bl[1]);
                    mma16816(acc[1][n0+1], a1, bl[2], bl[3]);
                }
            }
            if (ic < NCHUNK-2) BARARR(3 + s);     // buffer s free
        }

        // ---- epilogue: stage 256 o x 128 px through smem (stride 132) ----
        __syncthreads();
        float* ep = (float*)sm;
        const int qrow = lane >> 2;
        const int qcol = (lane & 3) * 2;
#pragma unroll
        for (int mt = 0; mt < 2; ++mt) {
#pragma unroll
            for (int nn = 0; nn < 8; ++nn) {
                int ol = wn*64 + nn*8 + qcol;
                int pr = wm*32 + mt*16 + qrow;
                ep[ol*132 + pr]          = acc[mt][nn][0];
                ep[(ol+1)*132 + pr]      = acc[mt][nn][1];
                ep[ol*132 + pr + 8]      = acc[mt][nn][2];
                ep[(ol+1)*132 + pr + 8]  = acc[mt][nn][3];
            }
        }
        __syncthreads();
#pragma unroll
        for (int i = 0; i < 16; ++i) {
            int idx = tid + i*512;
            int o = idx >> 5;
            int q = idx & 31;
            float bv = __ldg(&bias[o]);
            const float* er = ep + o*132 + q*4;
            float4 v = make_float4(er[0]+bv, er[1]+bv, er[2]+bv, er[3]+bv);
            *(float4*)(out + ((size_t)(b*OO + o))*HWP + p0 + q*4) = v;
        }
    }
}

extern "C" void kernel_launch(void* const* d_in, const int* in_sizes, int n_in,
                              void* d_out, int out_size) {
    const float* x    = (const float*)d_in[0];
    const float* w    = (const float*)d_in[1];
    const float* bias = (const float*)d_in[2];
    const float* spw  = (const float*)d_in[3];
    const float* spb  = (const float*)d_in[4];
    float* out = (float*)d_out;

    cudaFuncSetAttribute(k_main, cudaFuncAttributeMaxDynamicSharedMemorySize, SMEM_DYN);

    k_transpose<<<dim3(HWP/32, CC/32, BB), dim3(32, 8)>>>(x);
    k_wsplit  <<<(OO*KK)/256, 256>>>(w);
    k_spwt    <<<(2*9*256 + 255)/256, 256>>>(spw);
    k_spconv  <<<BB*(HH/16)*(WW/16), 256>>>(spb);
    k_main    <<<(BB*HWP)/MT, 640, SMEM_DYN>>>(bias, out);
}

// round 8
// speedup vs baseline: 2.4316x; 2.4316x over previous
#include <cuda_runtime.h>
#include <cuda_fp16.h>
#include <cstdint>

#define BB 4
#define CC 256
#define OO 256
#define HH 192
#define WW 192
#define HWP (HH*WW)          // 36864
#define KK 2304              // 9 taps * 256 ch
#define MT 64                // pixels per CTA tile
#define NCHUNK 36

// ---- scratch (__device__ globals: allocation-free) ----
__device__ __align__(16) __half g_xn[(size_t)BB*HWP*CC];   // NHWC x, fp16
__device__ float g_sx[BB*HWP];
__device__ float g_sy[BB*HWP];
__device__ __align__(16) __half g_wh[OO*KK];               // weight fp16, [o][t*256+c]
__device__ __align__(16) __half g_spwh[2*9*256];           // sp weights fp16 [ch][tap][c]

// ================= helpers (plain sm_80+ PTX only) =================
__device__ __forceinline__ uint32_t s2u(const void* p) {
    uint32_t a;
    asm("{ .reg .u64 t; cvta.to.shared.u64 t, %1; cvt.u32.u64 %0, t; }" : "=r"(a) : "l"(p));
    return a;
}
__device__ __forceinline__ uint32_t hpack(float lo, float hi) {
    uint32_t r;
    asm("cvt.rn.f16x2.f32 %0, %1, %2;" : "=r"(r) : "f"(hi), "f"(lo));
    return r;
}
__device__ __forceinline__ float2 h2f(uint32_t u) {
    __half2 h = *reinterpret_cast<__half2*>(&u);
    return __half22float2(h);
}
__device__ __forceinline__ void sts128u(uint32_t a, uint32_t x, uint32_t y, uint32_t z, uint32_t w) {
    asm volatile("st.shared.v4.b32 [%0], {%1, %2, %3, %4};"
                 :: "r"(a), "r"(x), "r"(y), "r"(z), "r"(w) : "memory");
}
__device__ __forceinline__ void ldm4(uint32_t* r, uint32_t a) {
    asm volatile("ldmatrix.sync.aligned.m8n8.x4.shared.b16 {%0,%1,%2,%3}, [%4];"
                 : "=r"(r[0]), "=r"(r[1]), "=r"(r[2]), "=r"(r[3]) : "r"(a));
}
__device__ __forceinline__ void mma16816(float* d, const uint32_t* a, uint32_t b0, uint32_t b1) {
    asm volatile("mma.sync.aligned.m16n8k16.row.col.f32.f16.f16.f32 "
                 "{%0,%1,%2,%3}, {%4,%5,%6,%7}, {%8,%9}, {%0,%1,%2,%3};"
                 : "+f"(d[0]), "+f"(d[1]), "+f"(d[2]), "+f"(d[3])
                 : "r"(a[0]), "r"(a[1]), "r"(a[2]), "r"(a[3]), "r"(b0), "r"(b1));
}
__device__ __forceinline__ void cpasync16(uint32_t dst, const void* src) {
    asm volatile("cp.async.cg.shared.global [%0], [%1], 16;"
                 :: "r"(dst), "l"(__cvta_generic_to_global(src)) : "memory");
}

// k_main smem layout (bytes)
#define OFF_A(s)   ((s)*8192)          // A: 2 x 64 rows x 128B (XOR-swizzled)
#define OFF_CRD    16384               // 8 x 64 x 4B = 2048
#define OFF_B(s)   (18432 + (s)*32768) // B: 2 x 256 rows x 128B (XOR-swizzled)
#define SMEM_DYN   83968

// ============ K1: NCHW -> NHWC fp16 transpose ============
__global__ void k_transpose(const float* __restrict__ x) {
    __shared__ float tile[32][33];
    int hw0 = blockIdx.x * 32, c0 = blockIdx.y * 32, b = blockIdx.z;
    int tx = threadIdx.x, ty = threadIdx.y;
#pragma unroll
    for (int i = 0; i < 4; ++i)
        tile[ty + i*8][tx] = x[(b*CC + c0 + ty + i*8)*HWP + hw0 + tx];
    __syncthreads();
#pragma unroll
    for (int i = 0; i < 4; ++i) {
        int hw = hw0 + ty + i*8;
        g_xn[((size_t)b*HWP + hw)*CC + c0 + tx] = __float2half_rn(tile[tx][ty + i*8]);
    }
}

// ============ K2: weight -> fp16 [o][t*256+c] ============
__global__ void k_whalf(const float* __restrict__ w) {
    int idx = blockIdx.x*256 + threadIdx.x;
    int o = idx / KK, k = idx - o*KK;
    int t = k >> 8, c = k & 255;
    g_wh[idx] = __float2half_rn(w[(o*CC + c)*9 + t]);
}

// ============ K2b: sp weight -> fp16 [ch][tap][c] ============
__global__ void k_spwt(const float* __restrict__ spw) {
    int i = blockIdx.x*256 + threadIdx.x;
    if (i >= 2*9*256) return;
    int ch = i / 2304, rem = i - ch*2304;
    int t = rem >> 8, c = rem & 255;
    g_spwh[i] = __float2half_rn(spw[(ch*CC + c)*9 + t]);
}

// ============ K3: scale-predictor conv, smem-tiled, fp16 data ============
// 256 thr = 16x16 pixel tile; halo 18x18; 8-ch chunks.
__global__ __launch_bounds__(256)
void k_spconv(const float* __restrict__ spb) {
    __shared__ __align__(16) __half ws[2*9*256];   // 9216 B
    __shared__ uint4 xs[324];                      // 5184 B, 18x18 px x 8ch fp16
    int tid = threadIdx.x;
    for (int i = tid; i < 576; i += 256)
        ((uint4*)ws)[i] = ((const uint4*)g_spwh)[i];

    int bx = blockIdx.x % (WW/16), rem = blockIdx.x / (WW/16);
    int by = rem % (HH/16), b = rem / (HH/16);
    int x0 = bx*16, y0 = by*16;
    int tx = tid & 15, ty = tid >> 4;

    float a0 = 0.f, a1 = 0.f;
    for (int cc = 0; cc < 32; ++cc) {
        __syncthreads();
        for (int tau = tid; tau < 324; tau += 256) {
            int py = tau / 18, px = tau - py*18;
            int gy = y0 + py - 1, gx = x0 + px - 1;
            uint4 v = make_uint4(0u, 0u, 0u, 0u);
            if (gy >= 0 && gy < HH && gx >= 0 && gx < WW)
                v = *(const uint4*)(g_xn + ((size_t)b*HWP + gy*WW + gx)*CC + cc*8);
            xs[tau] = v;
        }
        __syncthreads();
#pragma unroll
        for (int t = 0; t < 9; ++t) {
            uint4 xv = xs[(ty + t/3)*18 + tx + t%3];
            uint4 wa = *(const uint4*)(ws + t*256 + cc*8);
            uint4 wb = *(const uint4*)(ws + 2304 + t*256 + cc*8);
            const uint32_t* xw = &xv.x;
            const uint32_t* aw = &wa.x;
            const uint32_t* bw = &wb.x;
#pragma unroll
            for (int q = 0; q < 4; ++q) {
                float2 xf = h2f(xw[q]);
                float2 af = h2f(aw[q]);
                float2 bf = h2f(bw[q]);
                a0 += xf.x*af.x + xf.y*af.y;
                a1 += xf.x*bf.x + xf.y*bf.y;
            }
        }
    }
    int p = (b*HH + y0+ty)*WW + x0+tx;
    g_sx[p] = expf(fminf(fmaxf(a0 + spb[0], -2.f), 2.f));
    g_sy[p] = expf(fminf(fmaxf(a1 + spb[1], -2.f), 2.f));
}

// ============ K4: main — fp16 gather + single-term fp16 HMMA, 2 CTAs/SM ============
// 256 threads = 8 warps (2M x 4N). CTA tile M=64 px, N=256 out. B double-buffered prefetch.
__global__ void __launch_bounds__(256, 2)
k_main(const float* __restrict__ bias, float* __restrict__ out) {
    extern __shared__ char sm[];
    const uint32_t SMB = s2u(sm);
    int*   so00 = (int*)  (sm + OFF_CRD);
    int*   so01 = (int*)  (sm + OFF_CRD + 256);
    int*   so10 = (int*)  (sm + OFF_CRD + 512);
    int*   so11 = (int*)  (sm + OFF_CRD + 768);
    float* sw00 = (float*)(sm + OFF_CRD + 1024);
    float* sw01 = (float*)(sm + OFF_CRD + 1280);
    float* sw10 = (float*)(sm + OFF_CRD + 1536);
    float* sw11 = (float*)(sm + OFF_CRD + 1792);

    const int tid  = threadIdx.x;
    const int wid  = tid >> 5, lane = tid & 31;
    const int wm   = wid & 1;          // M group (32 rows)
    const int wn   = wid >> 1;         // N group (64 cols)
    const int m0 = blockIdx.x * MT;
    const int b  = m0 / HWP;
    const int pb = b * HWP;
    const int p0 = m0 - pb;
    // anti-phase skew between the 2 co-resident CTAs
    const int phase = ((blockIdx.x >> 2) & 1) * 16;

    // ldmatrix lane addressing (A and B both 128B-row XOR-swizzled)
    const int lrow = lane & 7;
    const int a_row16 = lrow + ((lane >> 3) & 1) * 8;
    const uint32_t arow0 = (uint32_t)(wm*32 + a_row16) * 128u;
    const uint32_t axor  = (uint32_t)lrow << 4;
    const uint32_t akk   = (uint32_t)(lane >> 4) * 16u;
    const int b_n   = (lane >> 4) * 8 + lrow;
    const int brow  = wn*64 + b_n;
    const uint32_t bbase = (uint32_t)brow * 128u;
    const uint32_t bxor  = ((uint32_t)brow & 7u) << 4;
    const uint32_t bkk   = ((lane >> 3) & 1) * 16u;

    float acc[2][8][4];
#pragma unroll
    for (int i = 0; i < 2; ++i)
#pragma unroll
        for (int j = 0; j < 8; ++j)
#pragma unroll
            for (int q = 0; q < 4; ++q) acc[i][j][q] = 0.f;

    // ---- prologue: prefetch B(first chunk) ----
    {
        const int kc0 = phase % NCHUNK;
        const uint32_t BD = SMB + OFF_B(0);
#pragma unroll
        for (int it = 0; it < 8; ++it) {
            int tau = tid + it*256;
            int r = tau >> 3, u = tau & 7;
            uint32_t off = (uint32_t)(r*128 + u*16);
            cpasync16(BD + (off ^ ((off >> 3) & 0x70u)),
                      g_wh + (size_t)r*KK + kc0*64 + u*8);
        }
        asm volatile("cp.async.commit_group;" ::: "memory");
    }

    for (int ic = 0; ic < NCHUNK; ++ic) {
        const int s = ic & 1;
        const int kc = (ic + phase) % NCHUNK;
        const int t = kc >> 2;
        const int cbase = (kc & 3) * 64;

        __syncthreads();   // prev MMA done: A and B[s^1] free

        if ((kc & 3) == 0) {     // new tap: bilinear coords (1 px/thread, tid<64)
            if (tid < MT) {
                int p = m0 + tid;
                int r = p - pb;
                int y = r / WW, xx = r - y*WW;
                float cx = (float)(t % 3 - 1), cy = (float)(t / 3 - 1);
                float gx = fminf(fmaxf((float)xx + cx*g_sx[p], 0.f), (float)(WW-1));
                float gy = fminf(fmaxf((float)y  + cy*g_sy[p], 0.f), (float)(HH-1));
                float x0f = floorf(gx), y0f = floorf(gy);
                float wx = gx - x0f, wy = gy - y0f;
                int ix0 = (int)x0f, iy0 = (int)y0f;
                int ix1 = min(ix0+1, WW-1), iy1 = min(iy0+1, HH-1);
                int r0 = pb + iy0*WW, r1 = pb + iy1*WW;
                so00[tid] = (r0 + ix0) * CC;
                so01[tid] = (r0 + ix1) * CC;
                so10[tid] = (r1 + ix0) * CC;
                so11[tid] = (r1 + ix1) * CC;
                sw00[tid] = (1.f-wx)*(1.f-wy);
                sw01[tid] = wx*(1.f-wy);
                sw10[tid] = (1.f-wx)*wy;
                sw11[tid] = wx*wy;
            }
            __syncthreads();
        }

        // ---- prefetch B(next chunk) into the other buffer ----
        if (ic + 1 < NCHUNK) {
            const int kcn = (ic + 1 + phase) % NCHUNK;
            const uint32_t BD = SMB + OFF_B(s ^ 1);
#pragma unroll
            for (int it = 0; it < 8; ++it) {
                int tau = tid + it*256;
                int r = tau >> 3, u = tau & 7;
                uint32_t off = (uint32_t)(r*128 + u*16);
                cpasync16(BD + (off ^ ((off >> 3) & 0x70u)),
                          g_wh + (size_t)r*KK + kcn*64 + u*8);
            }
            asm volatile("cp.async.commit_group;" ::: "memory");
        }

        // ---- A gather: 64 px x 64 ch fp16 -> swizzled 64x128B tile ----
        const uint32_t AT = SMB + OFF_A(s);
#pragma unroll
        for (int it = 0; it < 2; ++it) {
            int tau = tid + it*256;
            int p = tau >> 3;          // 0..63
            int j = tau & 7;           // 8-channel group
            int cb = cbase + j*8;
            uint4 u00 = *(const uint4*)(g_xn + (size_t)so00[p] + cb);
            uint4 u01 = *(const uint4*)(g_xn + (size_t)so01[p] + cb);
            uint4 u10 = *(const uint4*)(g_xn + (size_t)so10[p] + cb);
            uint4 u11 = *(const uint4*)(g_xn + (size_t)so11[p] + cb);
            float w00 = sw00[p], w01 = sw01[p], w10 = sw10[p], w11 = sw11[p];
            const uint32_t* a = &u00.x;
            const uint32_t* bb2 = &u01.x;
            const uint32_t* c = &u10.x;
            const uint32_t* d = &u11.x;
            uint32_t rr[4];
#pragma unroll
            for (int q = 0; q < 4; ++q) {
                float2 f00 = h2f(a[q]), f01 = h2f(bb2[q]);
                float2 f10 = h2f(c[q]), f11 = h2f(d[q]);
                float g0 = w00*f00.x + w01*f01.x + w10*f10.x + w11*f11.x;
                float g1 = w00*f00.y + w01*f01.y + w10*f10.y + w11*f11.y;
                rr[q] = hpack(g0, g1);
            }
            uint32_t off = (uint32_t)(p*128 + j*16);
            sts128u(AT + (off ^ ((off >> 3) & 0x70u)), rr[0], rr[1], rr[2], rr[3]);
        }

        if (ic + 1 < NCHUNK) {
            asm volatile("cp.async.wait_group 1;" ::: "memory");   // B(ic) ready
        } else {
            asm volatile("cp.async.wait_group 0;" ::: "memory");
        }
        __syncthreads();

        // ---- MMA: 4 k16 steps, single fp16 term ----
        const uint32_t BH = SMB + OFF_B(s);
#pragma unroll
        for (int ks = 0; ks < 4; ++ks) {
            uint32_t a0[4], a1[4];
            uint32_t ka = ((uint32_t)(ks*32) + akk) ^ axor;
            ldm4(a0, AT + arow0 + ka);
            ldm4(a1, AT + arow0 + 2048 + ka);
            uint32_t kb = ((uint32_t)(ks*32) + bkk) ^ bxor;
#pragma unroll
            for (int nt = 0; nt < 4; ++nt) {
                uint32_t bh[4];
                ldm4(bh, BH + bbase + nt*2048 + kb);
                int n0 = nt*2;
                mma16816(acc[0][n0],   a0, bh[0], bh[1]);
                mma16816(acc[0][n0+1], a0, bh[2], bh[3]);
                mma16816(acc[1][n0],   a1, bh[0], bh[1]);
                mma16816(acc[1][n0+1], a1, bh[2], bh[3]);
            }
        }
    }

    // ---- epilogue: stage 256 o x 64 px through smem (stride 68) ----
    __syncthreads();
    float* ep = (float*)sm;
    const int qrow = lane >> 2;
    const int qcol = (lane & 3) * 2;
#pragma unroll
    for (int mt = 0; mt < 2; ++mt) {
#pragma unroll
        for (int nn = 0; nn < 8; ++nn) {
            int ol = wn*64 + nn*8 + qcol;
            int pr = wm*32 + mt*16 + qrow;
            ep[ol*68 + pr]         = acc[mt][nn][0];
            ep[(ol+1)*68 + pr]     = acc[mt][nn][1];
            ep[ol*68 + pr + 8]     = acc[mt][nn][2];
            ep[(ol+1)*68 + pr + 8] = acc[mt][nn][3];
        }
    }
    __syncthreads();
#pragma unroll
    for (int i = 0; i < 16; ++i) {
        int o = i*16 + (tid >> 4);
        int q = tid & 15;
        float bv = __ldg(&bias[o]);
        const float* er = ep + o*68 + q*4;
        float4 v = make_float4(er[0]+bv, er[1]+bv, er[2]+bv, er[3]+bv);
        *(float4*)(out + ((size_t)(b*OO + o))*HWP + p0 + q*4) = v;
    }
}

extern "C" void kernel_launch(void* const* d_in, const int* in_sizes, int n_in,
                              void* d_out, int out_size) {
    const float* x    = (const float*)d_in[0];
    const float* w    = (const float*)d_in[1];
    const float* bias = (const float*)d_in[2];
    const float* spw  = (const float*)d_in[3];
    const float* spb  = (const float*)d_in[4];
    float* out = (float*)d_out;

    cudaFuncSetAttribute(k_main, cudaFuncAttributeMaxDynamicSharedMemorySize, SMEM_DYN);

    k_transpose<<<dim3(HWP/32, CC/32, BB), dim3(32, 8)>>>(x);
    k_whalf   <<<(OO*KK)/256, 256>>>(w);
    k_spwt    <<<(2*9*256 + 255)/256, 256>>>(spw);
    k_spconv  <<<BB*(HH/16)*(WW/16), 256>>>(spb);
    k_main    <<<(BB*HWP)/MT, 256, SMEM_DYN>>>(bias, out);
}